// round 16
// baseline (speedup 1.0000x reference)
#include <cuda_runtime.h>
#include <cuda_fp16.h>
#include <math.h>
#include <float.h>

#define BATCH 256
#define SEQL  200
#define DIM   256
#define G4    1024
#define NROWS (BATCH*SEQL)   // 51200
#define MB 32
#define NBLK 128             // 8 batch-tiles x 16 j-tiles
#define GRP 16               // blocks per barrier group (one batch-tile)

// scan smem geometry (fp16 path)
#define HKU 132              // [32][132] uints (128 k-pairs + 4 pad) -> conflict-free A frags
#define WKS 264              // weight k-stride in halves (132 uints)
#define WN  88               // gate scratch stride (f32)

// gemm fp16 smem geometry
#define GHK 20               // k-pair stride (16 + 4 pad) -> conflict-free frags

// ---------------- device scratch (no allocations allowed) ----------------
__device__ float g_x[NROWS*DIM];
__device__ float g_tfeat[NROWS*64];
__device__ float g_tf[NROWS*DIM];
__device__ float g_xu[NROWS*G4];
__device__ float g_outh[NROWS*DIM];
__device__ float g_whk[NROWS*DIM];
__device__ float g_att1[NROWS*64];
__device__ float g_attn[NROWS*2];
__device__ float g_genx[NROWS*DIM];
__device__ float g_ek[BATCH*DIM];
__device__ float g_ekw1[BATCH*64];
__device__ __half g_h16[2][BATCH*DIM];    // fp16 h (MMA operand)
__device__ float  g_cbuf[2][BATCH*DIM];   // exact f32 c
__device__ __half g_c16[2][BATCH*DIM];    // fp16 c (MMA operand)
__device__ float g_hmax[BATCH*DIM];
__device__ __half g_wpack16[16*80*WKS];   // [jblk][n][k] fp16 weights
__device__ unsigned g_bars[256];          // per-batch-group counters, stride 32 (128B)

// ---------------- fast-math helpers ----------------
__device__ __forceinline__ float ftanh(float x) {
    float y; asm("tanh.approx.f32 %0, %1;" : "=f"(y) : "f"(x)); return y;
}
__device__ __forceinline__ float fsig(float x) {
    return fmaf(0.5f, ftanh(0.5f * x), 0.5f);
}
__device__ __forceinline__ unsigned packh2(float a, float b) {
    __half2 h = __floats2half2_rn(a, b);
    return *(unsigned*)&h;
}

#define MMA16(acc, a0, a1, a2, a3, b0, b1) \
    asm volatile("mma.sync.aligned.m16n8k16.row.col.f32.f16.f16.f32 " \
                 "{%0,%1,%2,%3}, {%4,%5,%6,%7}, {%8,%9}, {%0,%1,%2,%3};" \
                 : "+f"(acc[0]), "+f"(acc[1]), "+f"(acc[2]), "+f"(acc[3]) \
                 : "r"(a0), "r"(a1), "r"(a2), "r"(a3), "r"(b0), "r"(b1))

// ---------------- fp16 tensor-core GEMM (parallel projections) ---------------
// 3 CTAs/SM target: more warps to hide sync + smem latency (R15: issue 28.6%).
__global__ void __launch_bounds__(256, 3)
gemm_f16(const float* __restrict__ A, const float* __restrict__ B,
         float* __restrict__ C,
         const float* __restrict__ bias0, const float* __restrict__ bias1,
         int M, int N, int K) {
    __shared__ unsigned As[128 * GHK];   // [m][kp]
    __shared__ unsigned Bs[64 * GHK];    // [n][kp]

    int tid  = threadIdx.x;
    int lane = tid & 31, wid = tid >> 5;
    int wm = wid & 3, wn = wid >> 2;
    int gid = lane >> 2, tid4 = lane & 3;
    int bm = blockIdx.y, bn = blockIdx.x;

    const float* Ab = A + (size_t)bm * 128 * K;
    const float* Bb = B + (size_t)bn * 64;

    int am[4], akq[4];
#pragma unroll
    for (int it = 0; it < 4; it++) { int f = it * 256 + tid; am[it] = f >> 3; akq[it] = f & 7; }
    int bkp[4], bnn[4];
#pragma unroll
    for (int it = 0; it < 4; it++) { int f = it * 256 + tid; bkp[it] = f >> 6; bnn[it] = f & 63; }

    float acc[2][4][4];
#pragma unroll
    for (int i = 0; i < 2; i++)
#pragma unroll
        for (int j = 0; j < 4; j++)
#pragma unroll
            for (int q = 0; q < 4; q++) acc[i][j][q] = 0.f;

    float4 ar[4];
    float2 br0[4];
#pragma unroll
    for (int it = 0; it < 4; it++)
        ar[it] = *(const float4*)(Ab + (size_t)am[it] * K + akq[it] * 4);
#pragma unroll
    for (int it = 0; it < 4; it++) {
        const float* p = Bb + (size_t)(bkp[it] * 2) * N + bnn[it];
        br0[it].x = p[0]; br0[it].y = p[N];
    }

    int nch = K >> 5;
    for (int ch = 0; ch < nch; ch++) {
#pragma unroll
        for (int it = 0; it < 4; it++) {
            unsigned* p = &As[am[it] * GHK + akq[it] * 2];
            p[0] = packh2(ar[it].x, ar[it].y);
            p[1] = packh2(ar[it].z, ar[it].w);
        }
#pragma unroll
        for (int it = 0; it < 4; it++)
            Bs[bnn[it] * GHK + bkp[it]] = packh2(br0[it].x, br0[it].y);
        __syncthreads();
        if (ch + 1 < nch) {
            int k0 = (ch + 1) << 5;
#pragma unroll
            for (int it = 0; it < 4; it++)
                ar[it] = *(const float4*)(Ab + (size_t)am[it] * K + k0 + akq[it] * 4);
#pragma unroll
            for (int it = 0; it < 4; it++) {
                const float* p = Bb + (size_t)(k0 + bkp[it] * 2) * N + bnn[it];
                br0[it].x = p[0]; br0[it].y = p[N];
            }
        }
#pragma unroll
        for (int ks = 0; ks < 2; ks++) {
            int kk = ks * 8;
            unsigned af[2][4], bf[4][2];
#pragma unroll
            for (int s = 0; s < 2; s++) {
                int rm = wm * 32 + s * 16 + gid;
                af[s][0] = As[rm * GHK + kk + tid4];
                af[s][1] = As[(rm + 8) * GHK + kk + tid4];
                af[s][2] = As[rm * GHK + kk + tid4 + 4];
                af[s][3] = As[(rm + 8) * GHK + kk + tid4 + 4];
            }
#pragma unroll
            for (int s = 0; s < 4; s++) {
                int cb = wn * 32 + s * 8 + gid;
                bf[s][0] = Bs[cb * GHK + kk + tid4];
                bf[s][1] = Bs[cb * GHK + kk + tid4 + 4];
            }
#pragma unroll
            for (int i = 0; i < 2; i++)
#pragma unroll
                for (int j = 0; j < 4; j++)
                    MMA16(acc[i][j], af[i][0], af[i][1], af[i][2], af[i][3],
                          bf[j][0], bf[j][1]);
        }
        __syncthreads();
    }

#pragma unroll
    for (int i = 0; i < 2; i++) {
        int r0 = bm * 128 + wm * 32 + i * 16 + gid;
#pragma unroll
        for (int j = 0; j < 4; j++) {
            int col = bn * 64 + wn * 32 + j * 8 + tid4 * 2;
            float bb0 = 0.f, bb1 = 0.f;
            if (bias0) { bb0 += bias0[col]; bb1 += bias0[col + 1]; }
            if (bias1) { bb0 += bias1[col]; bb1 += bias1[col + 1]; }
            float2 v0; v0.x = acc[i][j][0] + bb0; v0.y = acc[i][j][1] + bb1;
            float2 v1; v1.x = acc[i][j][2] + bb0; v1.y = acc[i][j][3] + bb1;
            *(float2*)(C + (size_t)r0 * N + col) = v0;
            *(float2*)(C + (size_t)(r0 + 8) * N + col) = v1;
        }
    }
}

// ---------------- fused prep: barrier reset + tfeat + fp16 weight pack -------
__global__ void k_prep(const float* __restrict__ seq_time, const float* __restrict__ sel_w,
                       const float* __restrict__ sel_b,
                       const float* __restrict__ Wall, const float* __restrict__ Wd) {
    int bid = blockIdx.x;
    if (bid == 0) g_bars[threadIdx.x] = 0;
    if (bid < 12800) {
        int idx = bid * 256 + threadIdx.x;
        int r = idx >> 6, n = idx & 63;
        float t = seq_time[r] * (1.0f / 180.0f);
        float q = t * sel_w[n] + sel_b[n];
        g_tfeat[idx] = 1.0f - ftanh(q * q);
    } else {
        int idx = (bid - 12800) * 256 + threadIdx.x;
        if (idx < 16 * 80 * 256) {
            int kpos = idx & 255;
            int rest = idx >> 8;
            int n = rest % 80;
            int jblk = rest / 80;
            float v;
            if (n < 64) v = Wall[(size_t)kpos * G4 + (n >> 4) * DIM + jblk * 16 + (n & 15)];
            else        v = Wd[(size_t)kpos * DIM + jblk * 16 + (n - 64)];
            g_wpack16[((size_t)(jblk * 80 + n)) * WKS + kpos] = __float2half_rn(v);
        }
    }
}

// ---------------- small elementwise kernels ----------------
__global__ void k_ek() {
    int idx = blockIdx.x * blockDim.x + threadIdx.x;
    if (idx >= BATCH * DIM) return;
    int b = idx >> 8, j = idx & 255;
    g_ek[idx] = g_x[(size_t)b * SEQL * DIM + j];
}

__global__ void k_ekw1(const float* __restrict__ w1_w) {
    int b = blockIdx.x;
    int n = threadIdx.x;  // 64
    float s = 0.f;
    const float* e = g_ek + b * DIM;
#pragma unroll 8
    for (int k = 0; k < DIM; k++) s += e[k] * w1_w[k * 64 + n];
    g_ekw1[b * 64 + n] = s;
}

__global__ void k_attn(const float* __restrict__ w2_w, const float* __restrict__ w2_b) {
    int idx = blockIdx.x * blockDim.x + threadIdx.x;
    if (idx >= BATCH * 199) return;
    int b = idx / 199, s = idx % 199;
    int row = b * SEQL + s;
    const float* a1 = g_att1 + (size_t)row * 64;
    const float* ew = g_ekw1 + b * 64;
    float l0 = w2_b[0], l1 = w2_b[1];
#pragma unroll 8
    for (int n = 0; n < 64; n++) {
        float v = ftanh(a1[n] + ew[n]);
        l0 += v * w2_w[n * 2];
        l1 += v * w2_w[n * 2 + 1];
    }
    float m = fmaxf(l0, l1);
    float e0 = __expf(l0 - m), e1 = __expf(l1 - m);
    float inv = 1.0f / (e0 + e1);
    g_attn[row * 2]     = e0 * inv;
    g_attn[row * 2 + 1] = e1 * inv;
}

// gen_x + fused output pass-throughs (pn -> out_pn, nn -> out_nn)
__global__ void k_genx(const float* __restrict__ nn, const float* __restrict__ pn,
                       float* __restrict__ out_pn, float* __restrict__ out_nn) {
    int idx = blockIdx.x * blockDim.x + threadIdx.x;
    if (idx >= NROWS * DIM) return;
    int j = idx & 255;
    int rs = idx >> 8;
    int b = rs / SEQL, s = rs % SEQL;
    float nnv = nn[idx];
    float pnv = pn[idx];
    float v;
    if (s == 0) {
        v = g_ek[b * DIM + j];
    } else {
        int row = b * SEQL + (s - 1);
        v = g_ek[b * DIM + j] * g_attn[row * 2] + g_whk[(size_t)row * DIM + j] * g_attn[row * 2 + 1];
    }
    g_genx[idx] = v + nnv - pnv;
    out_pn[idx] = pnv;
    out_nn[idx] = nnv;
}

__global__ void k_out(const float* __restrict__ out_w, const float* __restrict__ out_b,
                      float* __restrict__ dst) {
    int b = blockIdx.x;
    int j = threadIdx.x;  // 256
    float h = g_hmax[b * DIM + j];
    __shared__ float s0[256], s1[256];
    s0[j] = h * out_w[j * 2];
    s1[j] = h * out_w[j * 2 + 1];
    __syncthreads();
    for (int off = 128; off > 0; off >>= 1) {
        if (j < off) { s0[j] += s0[j + off]; s1[j] += s1[j + off]; }
        __syncthreads();
    }
    if (j == 0) {
        dst[b * 2]     = s0[0] + out_b[0];
        dst[b * 2 + 1] = s1[0] + out_b[1];
    }
}

// ---------------- persistent LSTM scan: fp16 m16n8k16 gate GEMM --------------
// (byte-identical to R15's passing kernel)
template <bool STORE>
__global__ void __launch_bounds__(256, 1)
lstm_scan(const float* __restrict__ Wd_b, unsigned barBase) {
    extern __shared__ float sm[];
    unsigned* Hsmu = (unsigned*)sm;          // [32][HKU] fp16x2
    unsigned* Csmu = Hsmu + 32 * HKU;        // [32][HKU] fp16x2
    unsigned* Wsmu = Csmu + 32 * HKU;        // [80][HKU] fp16x2 weights
    float* Gs = (float*)(Wsmu + 80 * HKU);   // [32][WN] f32 gate preacts

    int tid = threadIdx.x;
    int bx = blockIdx.x;
    int btile = bx & 7, jblk = bx >> 3;
    int b0 = btile * MB, j0 = jblk * 16;
    unsigned* bar = &g_bars[btile * 32];

    {
        const uint4* src = (const uint4*)(g_wpack16 + (size_t)jblk * 80 * WKS);
        uint4* dst = (uint4*)Wsmu;
        for (int i = tid; i < 80 * HKU / 4; i += 256) dst[i] = src[i];
    }

    int lane = tid & 31, wid = tid >> 5;
    int fr = lane >> 2, fc = lane & 3;
    int mt = wid & 1, q = wid >> 1;
    int m16 = mt * 16;
    bool has3 = (q < 2);
    int n0w = (q * 8 + fr) * HKU;
    int n1w = ((q + 4) * 8 + fr) * HKU;
    int n2w = ((8 + q) * 8 + fr) * HKU;

    int jl = tid & 15, ml = (tid >> 4) * 2;
    int j = j0 + jl;
    float wdb = Wd_b[j];
    float hmax0 = -FLT_MAX, hmax1 = -FLT_MAX;

    unsigned target = barBase + GRP;
    size_t row0base = (size_t)(b0 + ml) * SEQL;

    float xf0, xi0, xo0, xc0, xf1, xi1, xo1, xc1, ts0, ts1;
    {
        size_t r0 = row0base, r1 = r0 + SEQL;
        const float* x0 = g_xu + r0 * G4 + j;
        const float* x1 = g_xu + r1 * G4 + j;
        xf0 = __ldg(x0);          xf1 = __ldg(x1);
        xi0 = __ldg(x0 + DIM);    xi1 = __ldg(x1 + DIM);
        xo0 = __ldg(x0 + 2*DIM);  xo1 = __ldg(x1 + 2*DIM);
        xc0 = __ldg(x0 + 3*DIM);  xc1 = __ldg(x1 + 3*DIM);
        ts0 = __ldg(g_tf + r0 * DIM + j);
        ts1 = __ldg(g_tf + r1 * DIM + j);
    }

    for (int s = 0; s < SEQL; s++) {
        int p = s & 1;
        size_t row0 = row0base + s, row1 = row0 + SEQL;
        float cold0 = 0.f, cold1 = 0.f;

        float av[5][2];
#pragma unroll
        for (int g = 0; g < 5; g++) { av[g][0] = 0.f; av[g][1] = 0.f; }

        if (s > 0) {
            cold0 = __ldcg(g_cbuf[p] + (b0 + ml) * DIM + j);
            cold1 = __ldcg(g_cbuf[p] + (b0 + ml + 1) * DIM + j);

            const uint4* hin = (const uint4*)(g_h16[p] + b0 * DIM);
            const uint4* cin = (const uint4*)(g_c16[p] + b0 * DIM);
            for (int i = tid; i < 1024; i += 256) {
                int bb = i >> 5, c4 = (i & 31) * 4;
                *(uint4*)(Hsmu + bb * HKU + c4) = __ldcg(hin + i);
                *(uint4*)(Csmu + bb * HKU + c4) = __ldcg(cin + i);
            }
            __syncthreads();

            float acc0[4] = {0,0,0,0}, acc1[4] = {0,0,0,0}, acc2[4] = {0,0,0,0};
            const unsigned* Ar0 = Hsmu + (m16 + fr) * HKU;
            const unsigned* Ar1 = Hsmu + (m16 + fr + 8) * HKU;
            const unsigned* Cr0 = Csmu + (m16 + fr) * HKU;
            const unsigned* Cr1 = Csmu + (m16 + fr + 8) * HKU;
#pragma unroll 4
            for (int kk = 0; kk < 128; kk += 8) {
                unsigned a0 = Ar0[kk + fc];
                unsigned a1 = Ar1[kk + fc];
                unsigned a2 = Ar0[kk + fc + 4];
                unsigned a3 = Ar1[kk + fc + 4];
                unsigned b00 = Wsmu[n0w + kk + fc];
                unsigned b01 = Wsmu[n0w + kk + fc + 4];
                unsigned b10 = Wsmu[n1w + kk + fc];
                unsigned b11 = Wsmu[n1w + kk + fc + 4];
                MMA16(acc0, a0, a1, a2, a3, b00, b01);
                MMA16(acc1, a0, a1, a2, a3, b10, b11);
                if (has3) {
                    unsigned c0 = Cr0[kk + fc];
                    unsigned c1 = Cr1[kk + fc];
                    unsigned c2 = Cr0[kk + fc + 4];
                    unsigned c3 = Cr1[kk + fc + 4];
                    unsigned b20 = Wsmu[n2w + kk + fc];
                    unsigned b21 = Wsmu[n2w + kk + fc + 4];
                    MMA16(acc2, c0, c1, c2, c3, b20, b21);
                }
            }

            {
                int nc0 = q * 8 + 2 * fc;
                *(float2*)(Gs + (m16 + fr) * WN + nc0)     = make_float2(acc0[0], acc0[1]);
                *(float2*)(Gs + (m16 + fr + 8) * WN + nc0) = make_float2(acc0[2], acc0[3]);
                int nc1 = (q + 4) * 8 + 2 * fc;
                *(float2*)(Gs + (m16 + fr) * WN + nc1)     = make_float2(acc1[0], acc1[1]);
                *(float2*)(Gs + (m16 + fr + 8) * WN + nc1) = make_float2(acc1[2], acc1[3]);
                if (has3) {
                    int nc2 = (8 + q) * 8 + 2 * fc;
                    *(float2*)(Gs + (m16 + fr) * WN + nc2)     = make_float2(acc2[0], acc2[1]);
                    *(float2*)(Gs + (m16 + fr + 8) * WN + nc2) = make_float2(acc2[2], acc2[3]);
                }
            }
            __syncthreads();

#pragma unroll
            for (int g = 0; g < 5; g++) {
                int n = (g < 4) ? g * 16 + jl : 64 + jl;
                av[g][0] = Gs[ml * WN + n];
                av[g][1] = Gs[(ml + 1) * WN + n];
            }
        }

        float nf0 = 0, ni0 = 0, no0 = 0, nc0r = 0, nf1 = 0, ni1 = 0, no1 = 0, nc1r = 0;
        float nts0 = 0, nts1 = 0;
        if (s + 1 < SEQL) {
            size_t r0 = row0 + 1, r1 = row1 + 1;
            const float* x0 = g_xu + r0 * G4 + j;
            const float* x1 = g_xu + r1 * G4 + j;
            nf0 = __ldg(x0);          nf1 = __ldg(x1);
            ni0 = __ldg(x0 + DIM);    ni1 = __ldg(x1 + DIM);
            no0 = __ldg(x0 + 2*DIM);  no1 = __ldg(x1 + 2*DIM);
            nc0r = __ldg(x0 + 3*DIM); nc1r = __ldg(x1 + 3*DIM);
            nts0 = __ldg(g_tf + r0 * DIM + j);
            nts1 = __ldg(g_tf + r1 * DIM + j);
        }

        __half* Hd16 = g_h16[1 - p];
        float*  Cdst = g_cbuf[1 - p];
        __half* Cd16 = g_c16[1 - p];
        {
            float gf = fsig(av[0][0] + xf0);
            float gi = fsig(av[1][0] + xi0);
            float go = fsig(av[2][0] + xo0);
            float gc = fsig(av[3][0] + xc0);
            float cs1 = ftanh(av[4][0] + wdb);
            float cadj = cold0 - cs1 + cs1 * ts0;
            float cnew = gf * cadj + gi * gc;
            float hnew = go * ftanh(cnew);
            int oi = (b0 + ml) * DIM + j;
            Hd16[oi] = __float2half_rn(hnew);
            Cdst[oi] = cnew;
            Cd16[oi] = __float2half_rn(cnew);
            if (STORE) g_outh[row0 * DIM + j] = hnew;
            hmax0 = fmaxf(hmax0, hnew);
        }
        {
            float gf = fsig(av[0][1] + xf1);
            float gi = fsig(av[1][1] + xi1);
            float go = fsig(av[2][1] + xo1);
            float gc = fsig(av[3][1] + xc1);
            float cs1 = ftanh(av[4][1] + wdb);
            float cadj = cold1 - cs1 + cs1 * ts1;
            float cnew = gf * cadj + gi * gc;
            float hnew = go * ftanh(cnew);
            int oi = (b0 + ml + 1) * DIM + j;
            Hd16[oi] = __float2half_rn(hnew);
            Cdst[oi] = cnew;
            Cd16[oi] = __float2half_rn(cnew);
            if (STORE) g_outh[row1 * DIM + j] = hnew;
            hmax1 = fmaxf(hmax1, hnew);
        }

        xf0 = nf0; xi0 = ni0; xo0 = no0; xc0 = nc0r;
        xf1 = nf1; xi1 = ni1; xo1 = no1; xc1 = nc1r;
        ts0 = nts0; ts1 = nts1;

        if (s < SEQL - 1) {
            __syncthreads();
            if (tid == 0) {
                __threadfence();
                atomicAdd(bar, 1u);
                volatile unsigned* bp = bar;
                while (*bp < target) {}
                __threadfence();
            }
            __syncthreads();
            target += GRP;
        }
    }

    int oi0 = (b0 + ml) * DIM + j;
    g_hmax[oi0] = hmax0;
    g_hmax[oi0 + DIM] = hmax1;
}

// ---------------- host launcher ----------------
extern "C" void kernel_launch(void* const* d_in, const int* in_sizes, int n_in,
                              void* d_out, int out_size) {
    (void)in_sizes; (void)n_in; (void)out_size;
    const float* input_seqs = (const float*)d_in[0];
    const float* seq_time   = (const float*)d_in[3];
    const float* nn         = (const float*)d_in[6];
    const float* pn         = (const float*)d_in[7];
    const float* emb2_w = (const float*)d_in[9];
    const float* emb2_b = (const float*)d_in[10];
    const float* Wall_w = (const float*)d_in[11];
    const float* Wall_b = (const float*)d_in[12];
    const float* Uall_w = (const float*)d_in[13];
    const float* Uall_b = (const float*)d_in[14];
    const float* Wd_w   = (const float*)d_in[15];
    const float* Wd_b   = (const float*)d_in[16];
    const float* time_w = (const float*)d_in[17];
    const float* time_b = (const float*)d_in[18];
    const float* sel_w  = (const float*)d_in[19];
    const float* sel_b  = (const float*)d_in[20];
    const float* whk_w  = (const float*)d_in[21];
    const float* whk_b  = (const float*)d_in[22];
    const float* w1_w   = (const float*)d_in[23];
    const float* w1_b   = (const float*)d_in[24];
    const float* w2_w   = (const float*)d_in[25];
    const float* w2_b   = (const float*)d_in[26];
    const float* out_w  = (const float*)d_in[27];
    const float* out_b  = (const float*)d_in[28];
    float* out = (float*)d_out;

    float *px, *ptfeat, *ptf, *pxu, *pouth, *pwhk, *patt1, *pgenx;
    cudaGetSymbolAddress((void**)&px, g_x);
    cudaGetSymbolAddress((void**)&ptfeat, g_tfeat);
    cudaGetSymbolAddress((void**)&ptf, g_tf);
    cudaGetSymbolAddress((void**)&pxu, g_xu);
    cudaGetSymbolAddress((void**)&pouth, g_outh);
    cudaGetSymbolAddress((void**)&pwhk, g_whk);
    cudaGetSymbolAddress((void**)&patt1, g_att1);
    cudaGetSymbolAddress((void**)&pgenx, g_genx);

    const int SMEM_SCAN = (2 * 32 * HKU + 80 * HKU + 32 * WN) * 4;  // 87296 B
    cudaFuncSetAttribute((const void*)lstm_scan<true>,
                         cudaFuncAttributeMaxDynamicSharedMemorySize, SMEM_SCAN);
    cudaFuncSetAttribute((const void*)lstm_scan<false>,
                         cudaFuncAttributeMaxDynamicSharedMemorySize, SMEM_SCAN);

    dim3 t256(256);

    // 1: prep (barrier reset + tfeat + fp16 weight pack)
    k_prep<<<12800 + 1280, t256>>>(seq_time, sel_w, sel_b, Wall_w, Wd_w);
    // 2: tf = tfeat @ time_w + time_b
    gemm_f16<<<dim3(DIM / 64, NROWS / 128), t256>>>(ptfeat, time_w, ptf, time_b, nullptr,
                                                    NROWS, DIM, 64);
    // 3: x = input @ emb2 + b
    gemm_f16<<<dim3(DIM / 64, NROWS / 128), t256>>>(input_seqs, emb2_w, px, emb2_b, nullptr,
                                                    NROWS, DIM, DIM);
    // 4: xu1 = x @ Uall + (Uall_b + Wall_b)
    gemm_f16<<<dim3(G4 / 64, NROWS / 128), t256>>>(px, Uall_w, pxu, Uall_b, Wall_b,
                                                   NROWS, G4, DIM);
    // 5: LSTM scan 1
    lstm_scan<true><<<NBLK, t256, SMEM_SCAN>>>(Wd_b, 0u);
    // e_k + out head
    k_ek<<<(BATCH * DIM + 255) / 256, t256>>>();
    k_out<<<BATCH, t256>>>(out_w, out_b, out);  // out -> [0, 512)

    // whk, attention, gen_x (+fused pass-throughs)
    gemm_f16<<<dim3(DIM / 64, NROWS / 128), t256>>>(pouth, whk_w, pwhk, whk_b, nullptr,
                                                    NROWS, DIM, DIM);
    k_ekw1<<<BATCH, 64>>>(w1_w);
    gemm_f16<<<dim3(1, NROWS / 128), t256>>>(pwhk, w1_w + 256 * 64, patt1, w1_b, nullptr,
                                             NROWS, 64, DIM);
    k_attn<<<(BATCH * 199 + 255) / 256, t256>>>(w2_w, w2_b);
    k_genx<<<(NROWS * DIM + 255) / 256, t256>>>(nn, pn,
                                                out + 1024,
                                                out + 1024 + (size_t)NROWS * DIM);

    // xu2 = gen_x @ Uall + (Uall_b + Wall_b)
    gemm_f16<<<dim3(G4 / 64, NROWS / 128), t256>>>(pgenx, Uall_w, pxu, Uall_b, Wall_b,
                                                   NROWS, G4, DIM);
    // LSTM scan 2 (scan1 consumed 199*GRP arrivals per group counter)
    lstm_scan<false><<<NBLK, t256, SMEM_SCAN>>>(Wd_b, 199u * GRP);
    k_out<<<BATCH, t256>>>(out_w, out_b, out + 512);  // gen_out -> [512, 1024)
}

// round 17
// speedup vs baseline: 1.3772x; 1.3772x over previous
#include <cuda_runtime.h>
#include <cuda_fp16.h>
#include <math.h>
#include <float.h>

#define BATCH 256
#define SEQL  200
#define DIM   256
#define G4    1024
#define NROWS (BATCH*SEQL)   // 51200
#define MB 32
#define NBLK 128             // 8 batch-tiles x 16 j-tiles
#define GRP 16               // blocks per barrier group (one batch-tile)

// scan smem geometry (fp16 path)
#define HKU 132              // [32][132] uints (128 k-pairs + 4 pad) -> conflict-free A frags
#define WKS 264              // weight k-stride in halves (132 uints)
#define WN  88               // gate scratch stride (f32)

// gemm fp16 smem geometry
#define GHK 20               // k-pair stride (16 + 4 pad) -> conflict-free frags

// ---------------- device scratch (no allocations allowed) ----------------
__device__ float g_x[NROWS*DIM];
__device__ float g_tfeat[NROWS*64];
__device__ float g_tf[NROWS*DIM];
__device__ float g_xu[NROWS*G4];
__device__ float g_outh[NROWS*DIM];
__device__ float g_whk[NROWS*DIM];
__device__ float g_att1[NROWS*64];
__device__ float g_attn[NROWS*2];
__device__ float g_genx[NROWS*DIM];
__device__ float g_ek[BATCH*DIM];
__device__ float g_ekw1[BATCH*64];
__device__ __half g_h16[2][BATCH*DIM];    // fp16 h (MMA operand)
__device__ float  g_cbuf[2][BATCH*DIM];   // exact f32 c
__device__ __half g_c16[2][BATCH*DIM];    // fp16 c (MMA operand)
__device__ float g_hmax[BATCH*DIM];
__device__ __half g_wpack16[16*80*WKS];   // [jblk][n][k] fp16 weights
__device__ unsigned g_bars[256];          // per-batch-group counters, stride 32 (128B)

// ---------------- fast-math helpers ----------------
__device__ __forceinline__ float ftanh(float x) {
    float y; asm("tanh.approx.f32 %0, %1;" : "=f"(y) : "f"(x)); return y;
}
__device__ __forceinline__ float fsig(float x) {
    return fmaf(0.5f, ftanh(0.5f * x), 0.5f);
}
__device__ __forceinline__ unsigned packh2(float a, float b) {
    __half2 h = __floats2half2_rn(a, b);
    return *(unsigned*)&h;
}

#define MMA16(acc, a0, a1, a2, a3, b0, b1) \
    asm volatile("mma.sync.aligned.m16n8k16.row.col.f32.f16.f16.f32 " \
                 "{%0,%1,%2,%3}, {%4,%5,%6,%7}, {%8,%9}, {%0,%1,%2,%3};" \
                 : "+f"(acc[0]), "+f"(acc[1]), "+f"(acc[2]), "+f"(acc[3]) \
                 : "r"(a0), "r"(a1), "r"(a2), "r"(a3), "r"(b0), "r"(b1))

// ---------------- fp16 tensor-core GEMM (R15-proven: natural regs, 2 CTA/SM) --
__global__ void gemm_f16(const float* __restrict__ A, const float* __restrict__ B,
                         float* __restrict__ C,
                         const float* __restrict__ bias0, const float* __restrict__ bias1,
                         int M, int N, int K) {
    __shared__ unsigned As[128 * GHK];   // [m][kp]
    __shared__ unsigned Bs[64 * GHK];    // [n][kp]

    int tid  = threadIdx.x;
    int lane = tid & 31, wid = tid >> 5;
    int wm = wid & 3, wn = wid >> 2;
    int gid = lane >> 2, tid4 = lane & 3;
    int bm = blockIdx.y, bn = blockIdx.x;

    const float* Ab = A + (size_t)bm * 128 * K;
    const float* Bb = B + (size_t)bn * 64;

    int am[4], akq[4];
#pragma unroll
    for (int it = 0; it < 4; it++) { int f = it * 256 + tid; am[it] = f >> 3; akq[it] = f & 7; }
    int bkp[4], bnn[4];
#pragma unroll
    for (int it = 0; it < 4; it++) { int f = it * 256 + tid; bkp[it] = f >> 6; bnn[it] = f & 63; }

    float acc[2][4][4];
#pragma unroll
    for (int i = 0; i < 2; i++)
#pragma unroll
        for (int j = 0; j < 4; j++)
#pragma unroll
            for (int q = 0; q < 4; q++) acc[i][j][q] = 0.f;

    float4 ar[4];
    float2 br0[4];
#pragma unroll
    for (int it = 0; it < 4; it++)
        ar[it] = *(const float4*)(Ab + (size_t)am[it] * K + akq[it] * 4);
#pragma unroll
    for (int it = 0; it < 4; it++) {
        const float* p = Bb + (size_t)(bkp[it] * 2) * N + bnn[it];
        br0[it].x = p[0]; br0[it].y = p[N];
    }

    int nch = K >> 5;
    for (int ch = 0; ch < nch; ch++) {
#pragma unroll
        for (int it = 0; it < 4; it++) {
            unsigned* p = &As[am[it] * GHK + akq[it] * 2];
            p[0] = packh2(ar[it].x, ar[it].y);
            p[1] = packh2(ar[it].z, ar[it].w);
        }
#pragma unroll
        for (int it = 0; it < 4; it++)
            Bs[bnn[it] * GHK + bkp[it]] = packh2(br0[it].x, br0[it].y);
        __syncthreads();
        if (ch + 1 < nch) {
            int k0 = (ch + 1) << 5;
#pragma unroll
            for (int it = 0; it < 4; it++)
                ar[it] = *(const float4*)(Ab + (size_t)am[it] * K + k0 + akq[it] * 4);
#pragma unroll
            for (int it = 0; it < 4; it++) {
                const float* p = Bb + (size_t)(k0 + bkp[it] * 2) * N + bnn[it];
                br0[it].x = p[0]; br0[it].y = p[N];
            }
        }
#pragma unroll
        for (int ks = 0; ks < 2; ks++) {
            int kk = ks * 8;
            unsigned af[2][4], bf[4][2];
#pragma unroll
            for (int s = 0; s < 2; s++) {
                int rm = wm * 32 + s * 16 + gid;
                af[s][0] = As[rm * GHK + kk + tid4];
                af[s][1] = As[(rm + 8) * GHK + kk + tid4];
                af[s][2] = As[rm * GHK + kk + tid4 + 4];
                af[s][3] = As[(rm + 8) * GHK + kk + tid4 + 4];
            }
#pragma unroll
            for (int s = 0; s < 4; s++) {
                int cb = wn * 32 + s * 8 + gid;
                bf[s][0] = Bs[cb * GHK + kk + tid4];
                bf[s][1] = Bs[cb * GHK + kk + tid4 + 4];
            }
#pragma unroll
            for (int i = 0; i < 2; i++)
#pragma unroll
                for (int j = 0; j < 4; j++)
                    MMA16(acc[i][j], af[i][0], af[i][1], af[i][2], af[i][3],
                          bf[j][0], bf[j][1]);
        }
        __syncthreads();
    }

#pragma unroll
    for (int i = 0; i < 2; i++) {
        int r0 = bm * 128 + wm * 32 + i * 16 + gid;
#pragma unroll
        for (int j = 0; j < 4; j++) {
            int col = bn * 64 + wn * 32 + j * 8 + tid4 * 2;
            float bb0 = 0.f, bb1 = 0.f;
            if (bias0) { bb0 += bias0[col]; bb1 += bias0[col + 1]; }
            if (bias1) { bb0 += bias1[col]; bb1 += bias1[col + 1]; }
            float2 v0; v0.x = acc[i][j][0] + bb0; v0.y = acc[i][j][1] + bb1;
            float2 v1; v1.x = acc[i][j][2] + bb0; v1.y = acc[i][j][3] + bb1;
            *(float2*)(C + (size_t)r0 * N + col) = v0;
            *(float2*)(C + (size_t)(r0 + 8) * N + col) = v1;
        }
    }
}

// ---------------- fused prep: barrier reset + tfeat + fp16 weight pack -------
__global__ void k_prep(const float* __restrict__ seq_time, const float* __restrict__ sel_w,
                       const float* __restrict__ sel_b,
                       const float* __restrict__ Wall, const float* __restrict__ Wd) {
    int bid = blockIdx.x;
    if (bid == 0) g_bars[threadIdx.x] = 0;
    if (bid < 12800) {
        int idx = bid * 256 + threadIdx.x;
        int r = idx >> 6, n = idx & 63;
        float t = seq_time[r] * (1.0f / 180.0f);
        float q = t * sel_w[n] + sel_b[n];
        g_tfeat[idx] = 1.0f - ftanh(q * q);
    } else {
        int idx = (bid - 12800) * 256 + threadIdx.x;
        if (idx < 16 * 80 * 256) {
            int kpos = idx & 255;
            int rest = idx >> 8;
            int n = rest % 80;
            int jblk = rest / 80;
            float v;
            if (n < 64) v = Wall[(size_t)kpos * G4 + (n >> 4) * DIM + jblk * 16 + (n & 15)];
            else        v = Wd[(size_t)kpos * DIM + jblk * 16 + (n - 64)];
            g_wpack16[((size_t)(jblk * 80 + n)) * WKS + kpos] = __float2half_rn(v);
        }
    }
}

// ---------------- small elementwise kernels ----------------
__global__ void k_ek() {
    int idx = blockIdx.x * blockDim.x + threadIdx.x;
    if (idx >= BATCH * DIM) return;
    int b = idx >> 8, j = idx & 255;
    g_ek[idx] = g_x[(size_t)b * SEQL * DIM + j];
}

__global__ void k_ekw1(const float* __restrict__ w1_w) {
    int b = blockIdx.x;
    int n = threadIdx.x;  // 64
    float s = 0.f;
    const float* e = g_ek + b * DIM;
#pragma unroll 8
    for (int k = 0; k < DIM; k++) s += e[k] * w1_w[k * 64 + n];
    g_ekw1[b * 64 + n] = s;
}

__global__ void k_attn(const float* __restrict__ w2_w, const float* __restrict__ w2_b) {
    int idx = blockIdx.x * blockDim.x + threadIdx.x;
    if (idx >= BATCH * 199) return;
    int b = idx / 199, s = idx % 199;
    int row = b * SEQL + s;
    const float* a1 = g_att1 + (size_t)row * 64;
    const float* ew = g_ekw1 + b * 64;
    float l0 = w2_b[0], l1 = w2_b[1];
#pragma unroll 8
    for (int n = 0; n < 64; n++) {
        float v = ftanh(a1[n] + ew[n]);
        l0 += v * w2_w[n * 2];
        l1 += v * w2_w[n * 2 + 1];
    }
    float m = fmaxf(l0, l1);
    float e0 = __expf(l0 - m), e1 = __expf(l1 - m);
    float inv = 1.0f / (e0 + e1);
    g_attn[row * 2]     = e0 * inv;
    g_attn[row * 2 + 1] = e1 * inv;
}

// gen_x + fused output pass-throughs (pn -> out_pn, nn -> out_nn)
__global__ void k_genx(const float* __restrict__ nn, const float* __restrict__ pn,
                       float* __restrict__ out_pn, float* __restrict__ out_nn) {
    int idx = blockIdx.x * blockDim.x + threadIdx.x;
    if (idx >= NROWS * DIM) return;
    int j = idx & 255;
    int rs = idx >> 8;
    int b = rs / SEQL, s = rs % SEQL;
    float nnv = nn[idx];
    float pnv = pn[idx];
    float v;
    if (s == 0) {
        v = g_ek[b * DIM + j];
    } else {
        int row = b * SEQL + (s - 1);
        v = g_ek[b * DIM + j] * g_attn[row * 2] + g_whk[(size_t)row * DIM + j] * g_attn[row * 2 + 1];
    }
    g_genx[idx] = v + nnv - pnv;
    out_pn[idx] = pnv;
    out_nn[idx] = nnv;
}

__global__ void k_out(const float* __restrict__ out_w, const float* __restrict__ out_b,
                      float* __restrict__ dst) {
    int b = blockIdx.x;
    int j = threadIdx.x;  // 256
    float h = g_hmax[b * DIM + j];
    __shared__ float s0[256], s1[256];
    s0[j] = h * out_w[j * 2];
    s1[j] = h * out_w[j * 2 + 1];
    __syncthreads();
    for (int off = 128; off > 0; off >>= 1) {
        if (j < off) { s0[j] += s0[j + off]; s1[j] += s1[j + off]; }
        __syncthreads();
    }
    if (j == 0) {
        dst[b * 2]     = s0[0] + out_b[0];
        dst[b * 2 + 1] = s1[0] + out_b[1];
    }
}

// ---------------- persistent LSTM scan: fp16 m16n8k16 gate GEMM --------------
// (byte-identical to R15's passing kernel)
template <bool STORE>
__global__ void __launch_bounds__(256, 1)
lstm_scan(const float* __restrict__ Wd_b, unsigned barBase) {
    extern __shared__ float sm[];
    unsigned* Hsmu = (unsigned*)sm;          // [32][HKU] fp16x2
    unsigned* Csmu = Hsmu + 32 * HKU;        // [32][HKU] fp16x2
    unsigned* Wsmu = Csmu + 32 * HKU;        // [80][HKU] fp16x2 weights
    float* Gs = (float*)(Wsmu + 80 * HKU);   // [32][WN] f32 gate preacts

    int tid = threadIdx.x;
    int bx = blockIdx.x;
    int btile = bx & 7, jblk = bx >> 3;
    int b0 = btile * MB, j0 = jblk * 16;
    unsigned* bar = &g_bars[btile * 32];

    {
        const uint4* src = (const uint4*)(g_wpack16 + (size_t)jblk * 80 * WKS);
        uint4* dst = (uint4*)Wsmu;
        for (int i = tid; i < 80 * HKU / 4; i += 256) dst[i] = src[i];
    }

    int lane = tid & 31, wid = tid >> 5;
    int fr = lane >> 2, fc = lane & 3;
    int mt = wid & 1, q = wid >> 1;
    int m16 = mt * 16;
    bool has3 = (q < 2);
    int n0w = (q * 8 + fr) * HKU;
    int n1w = ((q + 4) * 8 + fr) * HKU;
    int n2w = ((8 + q) * 8 + fr) * HKU;

    int jl = tid & 15, ml = (tid >> 4) * 2;
    int j = j0 + jl;
    float wdb = Wd_b[j];
    float hmax0 = -FLT_MAX, hmax1 = -FLT_MAX;

    unsigned target = barBase + GRP;
    size_t row0base = (size_t)(b0 + ml) * SEQL;

    float xf0, xi0, xo0, xc0, xf1, xi1, xo1, xc1, ts0, ts1;
    {
        size_t r0 = row0base, r1 = r0 + SEQL;
        const float* x0 = g_xu + r0 * G4 + j;
        const float* x1 = g_xu + r1 * G4 + j;
        xf0 = __ldg(x0);          xf1 = __ldg(x1);
        xi0 = __ldg(x0 + DIM);    xi1 = __ldg(x1 + DIM);
        xo0 = __ldg(x0 + 2*DIM);  xo1 = __ldg(x1 + 2*DIM);
        xc0 = __ldg(x0 + 3*DIM);  xc1 = __ldg(x1 + 3*DIM);
        ts0 = __ldg(g_tf + r0 * DIM + j);
        ts1 = __ldg(g_tf + r1 * DIM + j);
    }

    for (int s = 0; s < SEQL; s++) {
        int p = s & 1;
        size_t row0 = row0base + s, row1 = row0 + SEQL;
        float cold0 = 0.f, cold1 = 0.f;

        float av[5][2];
#pragma unroll
        for (int g = 0; g < 5; g++) { av[g][0] = 0.f; av[g][1] = 0.f; }

        if (s > 0) {
            cold0 = __ldcg(g_cbuf[p] + (b0 + ml) * DIM + j);
            cold1 = __ldcg(g_cbuf[p] + (b0 + ml + 1) * DIM + j);

            const uint4* hin = (const uint4*)(g_h16[p] + b0 * DIM);
            const uint4* cin = (const uint4*)(g_c16[p] + b0 * DIM);
            for (int i = tid; i < 1024; i += 256) {
                int bb = i >> 5, c4 = (i & 31) * 4;
                *(uint4*)(Hsmu + bb * HKU + c4) = __ldcg(hin + i);
                *(uint4*)(Csmu + bb * HKU + c4) = __ldcg(cin + i);
            }
            __syncthreads();

            float acc0[4] = {0,0,0,0}, acc1[4] = {0,0,0,0}, acc2[4] = {0,0,0,0};
            const unsigned* Ar0 = Hsmu + (m16 + fr) * HKU;
            const unsigned* Ar1 = Hsmu + (m16 + fr + 8) * HKU;
            const unsigned* Cr0 = Csmu + (m16 + fr) * HKU;
            const unsigned* Cr1 = Csmu + (m16 + fr + 8) * HKU;
#pragma unroll 4
            for (int kk = 0; kk < 128; kk += 8) {
                unsigned a0 = Ar0[kk + fc];
                unsigned a1 = Ar1[kk + fc];
                unsigned a2 = Ar0[kk + fc + 4];
                unsigned a3 = Ar1[kk + fc + 4];
                unsigned b00 = Wsmu[n0w + kk + fc];
                unsigned b01 = Wsmu[n0w + kk + fc + 4];
                unsigned b10 = Wsmu[n1w + kk + fc];
                unsigned b11 = Wsmu[n1w + kk + fc + 4];
                MMA16(acc0, a0, a1, a2, a3, b00, b01);
                MMA16(acc1, a0, a1, a2, a3, b10, b11);
                if (has3) {
                    unsigned c0 = Cr0[kk + fc];
                    unsigned c1 = Cr1[kk + fc];
                    unsigned c2 = Cr0[kk + fc + 4];
                    unsigned c3 = Cr1[kk + fc + 4];
                    unsigned b20 = Wsmu[n2w + kk + fc];
                    unsigned b21 = Wsmu[n2w + kk + fc + 4];
                    MMA16(acc2, c0, c1, c2, c3, b20, b21);
                }
            }

            {
                int nc0 = q * 8 + 2 * fc;
                *(float2*)(Gs + (m16 + fr) * WN + nc0)     = make_float2(acc0[0], acc0[1]);
                *(float2*)(Gs + (m16 + fr + 8) * WN + nc0) = make_float2(acc0[2], acc0[3]);
                int nc1 = (q + 4) * 8 + 2 * fc;
                *(float2*)(Gs + (m16 + fr) * WN + nc1)     = make_float2(acc1[0], acc1[1]);
                *(float2*)(Gs + (m16 + fr + 8) * WN + nc1) = make_float2(acc1[2], acc1[3]);
                if (has3) {
                    int nc2 = (8 + q) * 8 + 2 * fc;
                    *(float2*)(Gs + (m16 + fr) * WN + nc2)     = make_float2(acc2[0], acc2[1]);
                    *(float2*)(Gs + (m16 + fr + 8) * WN + nc2) = make_float2(acc2[2], acc2[3]);
                }
            }
            __syncthreads();

#pragma unroll
            for (int g = 0; g < 5; g++) {
                int n = (g < 4) ? g * 16 + jl : 64 + jl;
                av[g][0] = Gs[ml * WN + n];
                av[g][1] = Gs[(ml + 1) * WN + n];
            }
        }

        float nf0 = 0, ni0 = 0, no0 = 0, nc0r = 0, nf1 = 0, ni1 = 0, no1 = 0, nc1r = 0;
        float nts0 = 0, nts1 = 0;
        if (s + 1 < SEQL) {
            size_t r0 = row0 + 1, r1 = row1 + 1;
            const float* x0 = g_xu + r0 * G4 + j;
            const float* x1 = g_xu + r1 * G4 + j;
            nf0 = __ldg(x0);          nf1 = __ldg(x1);
            ni0 = __ldg(x0 + DIM);    ni1 = __ldg(x1 + DIM);
            no0 = __ldg(x0 + 2*DIM);  no1 = __ldg(x1 + 2*DIM);
            nc0r = __ldg(x0 + 3*DIM); nc1r = __ldg(x1 + 3*DIM);
            nts0 = __ldg(g_tf + r0 * DIM + j);
            nts1 = __ldg(g_tf + r1 * DIM + j);
        }

        __half* Hd16 = g_h16[1 - p];
        float*  Cdst = g_cbuf[1 - p];
        __half* Cd16 = g_c16[1 - p];
        {
            float gf = fsig(av[0][0] + xf0);
            float gi = fsig(av[1][0] + xi0);
            float go = fsig(av[2][0] + xo0);
            float gc = fsig(av[3][0] + xc0);
            float cs1 = ftanh(av[4][0] + wdb);
            float cadj = cold0 - cs1 + cs1 * ts0;
            float cnew = gf * cadj + gi * gc;
            float hnew = go * ftanh(cnew);
            int oi = (b0 + ml) * DIM + j;
            Hd16[oi] = __float2half_rn(hnew);
            Cdst[oi] = cnew;
            Cd16[oi] = __float2half_rn(cnew);
            if (STORE) g_outh[row0 * DIM + j] = hnew;
            hmax0 = fmaxf(hmax0, hnew);
        }
        {
            float gf = fsig(av[0][1] + xf1);
            float gi = fsig(av[1][1] + xi1);
            float go = fsig(av[2][1] + xo1);
            float gc = fsig(av[3][1] + xc1);
            float cs1 = ftanh(av[4][1] + wdb);
            float cadj = cold1 - cs1 + cs1 * ts1;
            float cnew = gf * cadj + gi * gc;
            float hnew = go * ftanh(cnew);
            int oi = (b0 + ml + 1) * DIM + j;
            Hd16[oi] = __float2half_rn(hnew);
            Cdst[oi] = cnew;
            Cd16[oi] = __float2half_rn(cnew);
            if (STORE) g_outh[row1 * DIM + j] = hnew;
            hmax1 = fmaxf(hmax1, hnew);
        }

        xf0 = nf0; xi0 = ni0; xo0 = no0; xc0 = nc0r;
        xf1 = nf1; xi1 = ni1; xo1 = no1; xc1 = nc1r;
        ts0 = nts0; ts1 = nts1;

        if (s < SEQL - 1) {
            __syncthreads();
            if (tid == 0) {
                __threadfence();
                atomicAdd(bar, 1u);
                volatile unsigned* bp = bar;
                while (*bp < target) {}
                __threadfence();
            }
            __syncthreads();
            target += GRP;
        }
    }

    int oi0 = (b0 + ml) * DIM + j;
    g_hmax[oi0] = hmax0;
    g_hmax[oi0 + DIM] = hmax1;
}

// ---------------- host launcher ----------------
extern "C" void kernel_launch(void* const* d_in, const int* in_sizes, int n_in,
                              void* d_out, int out_size) {
    (void)in_sizes; (void)n_in; (void)out_size;
    const float* input_seqs = (const float*)d_in[0];
    const float* seq_time   = (const float*)d_in[3];
    const float* nn         = (const float*)d_in[6];
    const float* pn         = (const float*)d_in[7];
    const float* emb2_w = (const float*)d_in[9];
    const float* emb2_b = (const float*)d_in[10];
    const float* Wall_w = (const float*)d_in[11];
    const float* Wall_b = (const float*)d_in[12];
    const float* Uall_w = (const float*)d_in[13];
    const float* Uall_b = (const float*)d_in[14];
    const float* Wd_w   = (const float*)d_in[15];
    const float* Wd_b   = (const float*)d_in[16];
    const float* time_w = (const float*)d_in[17];
    const float* time_b = (const float*)d_in[18];
    const float* sel_w  = (const float*)d_in[19];
    const float* sel_b  = (const float*)d_in[20];
    const float* whk_w  = (const float*)d_in[21];
    const float* whk_b  = (const float*)d_in[22];
    const float* w1_w   = (const float*)d_in[23];
    const float* w1_b   = (const float*)d_in[24];
    const float* w2_w   = (const float*)d_in[25];
    const float* w2_b   = (const float*)d_in[26];
    const float* out_w  = (const float*)d_in[27];
    const float* out_b  = (const float*)d_in[28];
    float* out = (float*)d_out;

    float *px, *ptfeat, *ptf, *pxu, *pouth, *pwhk, *patt1, *pgenx;
    cudaGetSymbolAddress((void**)&px, g_x);
    cudaGetSymbolAddress((void**)&ptfeat, g_tfeat);
    cudaGetSymbolAddress((void**)&ptf, g_tf);
    cudaGetSymbolAddress((void**)&pxu, g_xu);
    cudaGetSymbolAddress((void**)&pouth, g_outh);
    cudaGetSymbolAddress((void**)&pwhk, g_whk);
    cudaGetSymbolAddress((void**)&patt1, g_att1);
    cudaGetSymbolAddress((void**)&pgenx, g_genx);

    const int SMEM_SCAN = (2 * 32 * HKU + 80 * HKU + 32 * WN) * 4;  // 87296 B
    cudaFuncSetAttribute((const void*)lstm_scan<true>,
                         cudaFuncAttributeMaxDynamicSharedMemorySize, SMEM_SCAN);
    cudaFuncSetAttribute((const void*)lstm_scan<false>,
                         cudaFuncAttributeMaxDynamicSharedMemorySize, SMEM_SCAN);

    dim3 t256(256);

    // 1: prep (barrier reset + tfeat + fp16 weight pack)
    k_prep<<<12800 + 1280, t256>>>(seq_time, sel_w, sel_b, Wall_w, Wd_w);
    // 2: tf = tfeat @ time_w + time_b
    gemm_f16<<<dim3(DIM / 64, NROWS / 128), t256>>>(ptfeat, time_w, ptf, time_b, nullptr,
                                                    NROWS, DIM, 64);
    // 3: x = input @ emb2 + b
    gemm_f16<<<dim3(DIM / 64, NROWS / 128), t256>>>(input_seqs, emb2_w, px, emb2_b, nullptr,
                                                    NROWS, DIM, DIM);
    // 4: xu1 = x @ Uall + (Uall_b + Wall_b)
    gemm_f16<<<dim3(G4 / 64, NROWS / 128), t256>>>(px, Uall_w, pxu, Uall_b, Wall_b,
                                                   NROWS, G4, DIM);
    // 5: LSTM scan 1
    lstm_scan<true><<<NBLK, t256, SMEM_SCAN>>>(Wd_b, 0u);
    // e_k + out head
    k_ek<<<(BATCH * DIM + 255) / 256, t256>>>();
    k_out<<<BATCH, t256>>>(out_w, out_b, out);  // out -> [0, 512)

    // whk, attention, gen_x (+fused pass-throughs)
    gemm_f16<<<dim3(DIM / 64, NROWS / 128), t256>>>(pouth, whk_w, pwhk, whk_b, nullptr,
                                                    NROWS, DIM, DIM);
    k_ekw1<<<BATCH, 64>>>(w1_w);
    gemm_f16<<<dim3(1, NROWS / 128), t256>>>(pwhk, w1_w + 256 * 64, patt1, w1_b, nullptr,
                                             NROWS, 64, DIM);
    k_attn<<<(BATCH * 199 + 255) / 256, t256>>>(w2_w, w2_b);
    k_genx<<<(NROWS * DIM + 255) / 256, t256>>>(nn, pn,
                                                out + 1024,
                                                out + 1024 + (size_t)NROWS * DIM);

    // xu2 = gen_x @ Uall + (Uall_b + Wall_b)
    gemm_f16<<<dim3(G4 / 64, NROWS / 128), t256>>>(pgenx, Uall_w, pxu, Uall_b, Wall_b,
                                                   NROWS, G4, DIM);
    // LSTM scan 2 (scan1 consumed 199*GRP arrivals per group counter)
    lstm_scan<false><<<NBLK, t256, SMEM_SCAN>>>(Wd_b, 199u * GRP);
    k_out<<<BATCH, t256>>>(out_w, out_b, out + 512);  // gen_out -> [512, 1024)
}